// round 7
// baseline (speedup 1.0000x reference)
#include <cuda_runtime.h>

#define B 4
#define C 19
#define H 192
#define W 192
#define HW (H*W)
// 40 * log2(e): exp(-40*x) == exp2(-THC*x)
#define THC 57.70780163555853f
#define SEG 6          // elements per lane; 32*6 = 192 = chain length
#define TW 32          // column-tile width
#define NBLK 456       // = B*C*(W/TW) column tiles; 8 warps/block * 4 = row chains

// ---------------------------------------------------------------------------
// Static scratch (allocations forbidden)
// ---------------------------------------------------------------------------
__device__ float g_d   [B*HW];                 // decay per pixel
__device__ float g_zc  [B*HW];                 // column Z (incl diag)
__device__ float g_zr  [B*HW];                 // row Z (diag removed)
__device__ float g_invz[B*HW];                 // 1/(zc+zr)
__device__ float g_colA[(size_t)B*C*HW];       // column aggregation result
__device__ float g_featA[(size_t)B*C*HW];      // ping
__device__ float g_featB[(size_t)B*C*HW];      // pong

// software grid barrier state
__device__ unsigned g_count = 0;
__device__ unsigned g_gen = 0;

__device__ __forceinline__ void grid_bar() {
    __syncthreads();
    __threadfence();                            // release by EVERY thread
    if (threadIdx.x == 0) {
        unsigned gen = atomicAdd(&g_gen, 0u);   // snapshot before arriving
        unsigned t = atomicAdd(&g_count, 1u);
        if (t == NBLK - 1) {
            atomicExch(&g_count, 0u);
            atomicAdd(&g_gen, 1u);              // release the pack
        } else {
            while (atomicAdd(&g_gen, 0u) == gen) { __nanosleep(64); }
        }
    }
    __syncthreads();
    __threadfence();                            // acquire by EVERY thread (L1 invalidate)
}

// inclusive warp scan of segment transfer (A, F):  f_out = A*f_in + F
__device__ __forceinline__ void wscan_fwd(float& A, float& F, int lane) {
    #pragma unroll
    for (int dl = 1; dl < 32; dl <<= 1) {
        float oa = __shfl_up_sync(0xffffffffu, A, dl);
        float of = __shfl_up_sync(0xffffffffu, F, dl);
        if (lane >= dl) { F = fmaf(of, A, F); A = oa * A; }
    }
}
__device__ __forceinline__ void wscan_bwd(float& A, float& G, int lane) {
    #pragma unroll
    for (int dl = 1; dl < 32; dl <<= 1) {
        float oa = __shfl_down_sync(0xffffffffu, A, dl);
        float og = __shfl_down_sync(0xffffffffu, G, dl);
        if (lane < 32 - dl) { G = fmaf(A, og, G); A = oa * A; }
    }
}

// ---------------------------------------------------------------------------
// Z chain: wg in [0, 2*B*W). mode 0: column Z; mode 1: row Z (diag removed)
// ---------------------------------------------------------------------------
__device__ void z_chain(int wg, int lane) {
    int mode = (wg >= B * W);
    int w2 = mode ? wg - B * W : wg;
    int b = w2 / W, q = w2 % W;

    const float* dp; float* zp; int st;
    if (!mode) { dp = g_d + b * HW + q + lane * SEG * W; zp = g_zc + b * HW + q + lane * SEG * W; st = W; }
    else       { dp = g_d + b * HW + q * W + lane * SEG; zp = g_zr + b * HW + q * W + lane * SEG; st = 1; }

    float d[SEG];
    #pragma unroll
    for (int k = 0; k < SEG; ++k) d[k] = dp[k * st];

    float F = 0.f, A = 1.f;
    #pragma unroll
    for (int k = 0; k < SEG; ++k) { F = fmaf(F, d[k], 1.f); A *= d[k]; }
    float Af = A;
    wscan_fwd(Af, F, lane);
    float fin = __shfl_up_sync(0xffffffffu, F, 1);
    if (lane == 0) fin = 0.f;
    float f[SEG], v = fin;
    #pragma unroll
    for (int k = 0; k < SEG; ++k) { v = fmaf(v, d[k], 1.f); f[k] = v; }

    float G = 0.f, Ab = A;
    #pragma unroll
    for (int k = SEG - 1; k >= 0; --k) G = (G + 1.f) * d[k];
    wscan_bwd(Ab, G, lane);
    float gin = __shfl_down_sync(0xffffffffu, G, 1);
    if (lane == 31) gin = 0.f;

    const float sub = mode ? 1.f : 0.f;
    float g = gin;
    #pragma unroll
    for (int k = SEG - 1; k >= 0; --k) {
        zp[k * st] = f[k] + g - sub;
        g = (g + 1.f) * d[k];
    }
}

// ---------------------------------------------------------------------------
// Column tile: block bid handles (b, c, 32-col tile); smem staged, coalesced.
// ---------------------------------------------------------------------------
__device__ void col_tile(const float* __restrict__ xsrc, float* xs, float* ds) {
    const int bid = blockIdx.x;
    const int j0 = (bid % (W / TW)) * TW;
    const int c  = (bid / (W / TW)) % C;
    const int b  = bid / ((W / TW) * C);
    const int tid = threadIdx.x;
    const int lane = tid & 31, wid = tid >> 5;

    const size_t base = ((size_t)(b * C + c) * H) * W + j0;
    const float* xg = xsrc + base;
    const float* dg = g_d + b * HW + j0;

    #pragma unroll 4
    for (int i = wid; i < H; i += 8) {
        int sw = i * TW + (lane ^ (i & 31));
        xs[sw] = xg[(size_t)i * W + lane];
        ds[sw] = dg[i * W + lane];
    }
    __syncthreads();

    #pragma unroll
    for (int cc = 0; cc < 4; ++cc) {
        const int jl = wid * 4 + cc;
        float x[SEG], d[SEG];
        #pragma unroll
        for (int k = 0; k < SEG; ++k) {
            int i = lane * SEG + k;
            int sw = i * TW + (jl ^ (i & 31));
            x[k] = xs[sw]; d[k] = ds[sw];
        }

        float F = 0.f, A = 1.f;
        #pragma unroll
        for (int k = 0; k < SEG; ++k) { F = fmaf(F, d[k], x[k]); A *= d[k]; }
        float Af = A;
        wscan_fwd(Af, F, lane);
        float fin = __shfl_up_sync(0xffffffffu, F, 1);
        if (lane == 0) fin = 0.f;
        float f[SEG], v = fin;
        #pragma unroll
        for (int k = 0; k < SEG; ++k) { v = fmaf(v, d[k], x[k]); f[k] = v; }

        float G = 0.f, Ab = A;
        #pragma unroll
        for (int k = SEG - 1; k >= 0; --k) G = (G + x[k]) * d[k];
        wscan_bwd(Ab, G, lane);
        float gin = __shfl_down_sync(0xffffffffu, G, 1);
        if (lane == 31) gin = 0.f;

        float g = gin;
        #pragma unroll
        for (int k = SEG - 1; k >= 0; --k) {
            int i = lane * SEG + k;
            xs[i * TW + (jl ^ (i & 31))] = f[k] + g;
            g = (g + x[k]) * d[k];
        }
    }
    __syncthreads();

    float* ag = g_colA + base;
    #pragma unroll 4
    for (int i = wid; i < H; i += 8) {
        int sw = i * TW + (lane ^ (i & 31));
        ag[(size_t)i * W + lane] = xs[sw];
    }
}

// ---------------------------------------------------------------------------
// Row chain + combine + normalize: chain id in [0, B*C*H) along j.
// ---------------------------------------------------------------------------
__device__ void row_chain(int ch, int lane, const float* __restrict__ xsrc,
                          float* __restrict__ ob) {
    int b = ch / (C * H);
    int r = ch - b * (C * H);
    int c = r / H;
    int i = r - c * H;

    size_t off = ((size_t)(b * C + c) * H + i) * W + lane * SEG;
    size_t ro  = (size_t)(b * H + i) * W + lane * SEG;

    const float2* xp = (const float2*)(xsrc + off);
    const float2* dp = (const float2*)(g_d + ro);
    const float2* ap = (const float2*)(g_colA + off);
    const float2* zp = (const float2*)(g_invz + ro);

    float x[SEG], d[SEG], a[SEG], z[SEG];
    #pragma unroll
    for (int k = 0; k < SEG / 2; ++k) { float2 t = xp[k]; x[2*k] = t.x; x[2*k+1] = t.y; }
    #pragma unroll
    for (int k = 0; k < SEG / 2; ++k) { float2 t = dp[k]; d[2*k] = t.x; d[2*k+1] = t.y; }
    #pragma unroll
    for (int k = 0; k < SEG / 2; ++k) { float2 t = ap[k]; a[2*k] = t.x; a[2*k+1] = t.y; }
    #pragma unroll
    for (int k = 0; k < SEG / 2; ++k) { float2 t = zp[k]; z[2*k] = t.x; z[2*k+1] = t.y; }

    float F = 0.f, A = 1.f;
    #pragma unroll
    for (int k = 0; k < SEG; ++k) { F = fmaf(F, d[k], x[k]); A *= d[k]; }
    float Af = A;
    wscan_fwd(Af, F, lane);
    float fin = __shfl_up_sync(0xffffffffu, F, 1);
    if (lane == 0) fin = 0.f;
    float f[SEG], v = fin;
    #pragma unroll
    for (int k = 0; k < SEG; ++k) { v = fmaf(v, d[k], x[k]); f[k] = v; }

    float G = 0.f, Ab = A;
    #pragma unroll
    for (int k = SEG - 1; k >= 0; --k) G = (G + x[k]) * d[k];
    wscan_bwd(Ab, G, lane);
    float gin = __shfl_down_sync(0xffffffffu, G, 1);
    if (lane == 31) gin = 0.f;

    float o[SEG], g = gin;
    #pragma unroll
    for (int k = SEG - 1; k >= 0; --k) {
        o[k] = (a[k] + f[k] + g - x[k]) * z[k];
        g = (g + x[k]) * d[k];
    }

    float2* op = (float2*)(ob + off);
    #pragma unroll
    for (int k = 0; k < SEG / 2; ++k)
        op[k] = make_float2(o[2*k], o[2*k+1]);
}

__device__ __forceinline__ void row_phase(int wg, int lane,
                                          const float* __restrict__ xsrc,
                                          float* __restrict__ ob) {
    #pragma unroll
    for (int q = 0; q < 4; ++q)                 // 3648 warps x 4 = 14592 chains
        row_chain(wg * 4 + q, lane, xsrc, ob);
}

// ---------------------------------------------------------------------------
// The whole pipeline in one persistent launch. iter fixed at 3.
// ---------------------------------------------------------------------------
__global__ __launch_bounds__(256, 4) void k_all(const float* __restrict__ mask,
                                                const float* __restrict__ edge,
                                                float* __restrict__ out) {
    __shared__ float sm[2 * H * TW];      // 48 KB
    float* xs = sm;
    float* ds = sm + H * TW;

    const int bid = blockIdx.x;
    const int tid = threadIdx.x;
    const int lane = tid & 31;
    const int wg = bid * 8 + (tid >> 5);

    // Phase A: decay
    for (int t = bid * 256 + tid; t < B * HW; t += NBLK * 256)
        g_d[t] = exp2f(-THC * fmaxf(edge[t], 0.f));
    grid_bar();

    // Phase B: Z chains (first 1536 warps) + column pass of iter 1
    if (wg < 2 * B * W) z_chain(wg, lane);
    col_tile(mask, xs, ds);
    grid_bar();

    // Phase C: invz
    for (int t = bid * 256 + tid; t < B * HW; t += NBLK * 256)
        g_invz[t] = 1.f / (g_zc[t] + g_zr[t]);
    grid_bar();

    // iter 1 row: mask -> featA
    row_phase(wg, lane, mask, g_featA);
    grid_bar();

    // iter 2
    col_tile(g_featA, xs, ds);
    grid_bar();
    row_phase(wg, lane, g_featA, g_featB);
    grid_bar();

    // iter 3
    col_tile(g_featB, xs, ds);
    grid_bar();
    row_phase(wg, lane, g_featB, out);
}

extern "C" void kernel_launch(void* const* d_in, const int* in_sizes, int n_in,
                              void* d_out, int out_size) {
    const float* mask = (const float*)d_in[0];
    const float* edge = (const float*)d_in[1];
    float* out = (float*)d_out;

    k_all<<<NBLK, 256>>>(mask, edge, out);
}

// round 8
// speedup vs baseline: 1.0649x; 1.0649x over previous
#include <cuda_runtime.h>

#define B 4
#define C 19
#define H 192
#define W 192
#define HW (H*W)
// 40 * log2(e): exp(-40*x) == exp2(-THC*x)
#define THC 57.70780163555853f
#define SEG 6          // elements per lane; 32*6 = 192 = chain length
#define TW 32          // column-tile width
#define NBLK 456       // = B*C*(W/TW) column tiles; co-resident at 4 blocks/SM

// ---------------------------------------------------------------------------
// Static scratch (allocations forbidden)
// ---------------------------------------------------------------------------
__device__ float g_zc  [B*HW];                 // column Z (incl diag), edge-only
__device__ float g_colA[(size_t)B*C*HW];       // column aggregation result
__device__ float g_featA[(size_t)B*C*HW];      // ping
__device__ float g_featB[(size_t)B*C*HW];      // pong

// software grid barrier state
__device__ unsigned g_count = 0;
__device__ unsigned g_gen = 0;

// CG-style grid barrier: thread-0 release/acquire atomics + one block fence.
__device__ __forceinline__ void grid_bar() {
    __syncthreads();
    if (threadIdx.x == 0) {
        unsigned gen;
        asm volatile("ld.acquire.gpu.u32 %0, [%1];" : "=r"(gen) : "l"(&g_gen) : "memory");
        unsigned t;
        asm volatile("atom.add.release.gpu.u32 %0, [%1], %2;"
                     : "=r"(t) : "l"(&g_count), "r"(1u) : "memory");
        if (t == NBLK - 1) {
            asm volatile("st.relaxed.gpu.u32 [%0], %1;" :: "l"(&g_count), "r"(0u) : "memory");
            asm volatile("red.add.release.gpu.u32 [%0], %1;" :: "l"(&g_gen), "r"(1u) : "memory");
        } else {
            unsigned cur;
            do {
                __nanosleep(32);
                asm volatile("ld.acquire.gpu.u32 %0, [%1];" : "=r"(cur) : "l"(&g_gen) : "memory");
            } while (cur == gen);
        }
        asm volatile("fence.acq_rel.gpu;" ::: "memory");   // SM-wide L1 hygiene
    }
    __syncthreads();
}

// warp scans of segment transfer (A, F): f_out = A*f_in + F
__device__ __forceinline__ void wscan_fwd(float& A, float& F, int lane) {
    #pragma unroll
    for (int dl = 1; dl < 32; dl <<= 1) {
        float oa = __shfl_up_sync(0xffffffffu, A, dl);
        float of = __shfl_up_sync(0xffffffffu, F, dl);
        if (lane >= dl) { F = fmaf(of, A, F); A = oa * A; }
    }
}
__device__ __forceinline__ void wscan_bwd(float& A, float& G, int lane) {
    #pragma unroll
    for (int dl = 1; dl < 32; dl <<= 1) {
        float oa = __shfl_down_sync(0xffffffffu, A, dl);
        float og = __shfl_down_sync(0xffffffffu, G, dl);
        if (lane < 32 - dl) { G = fmaf(A, og, G); A = oa * A; }
    }
}
// dual-payload versions (x-scan and ones-scan share A)
__device__ __forceinline__ void wscan_fwd2(float& A, float& F, float& F1, int lane) {
    #pragma unroll
    for (int dl = 1; dl < 32; dl <<= 1) {
        float oa = __shfl_up_sync(0xffffffffu, A, dl);
        float of = __shfl_up_sync(0xffffffffu, F, dl);
        float og = __shfl_up_sync(0xffffffffu, F1, dl);
        if (lane >= dl) { F = fmaf(of, A, F); F1 = fmaf(og, A, F1); A = oa * A; }
    }
}
__device__ __forceinline__ void wscan_bwd2(float& A, float& G, float& G1, int lane) {
    #pragma unroll
    for (int dl = 1; dl < 32; dl <<= 1) {
        float oa = __shfl_down_sync(0xffffffffu, A, dl);
        float og = __shfl_down_sync(0xffffffffu, G, dl);
        float oh = __shfl_down_sync(0xffffffffu, G1, dl);
        if (lane < 32 - dl) { G = fmaf(A, og, G); G1 = fmaf(A, oh, G1); A = oa * A; }
    }
}

// ---------------------------------------------------------------------------
// Column tile: block handles (b, c, 32-col tile). d computed inline from edge.
// If do_zc and c==0, also produces g_zc for this (b, j-tile).
// ---------------------------------------------------------------------------
__device__ void col_tile(const float* __restrict__ xsrc,
                         const float* __restrict__ edge,
                         float* xs, float* ds, int do_zc) {
    const int bid = blockIdx.x;
    const int j0 = (bid % (W / TW)) * TW;
    const int c  = (bid / (W / TW)) % C;
    const int b  = bid / ((W / TW) * C);
    const int tid = threadIdx.x;
    const int lane = tid & 31, wid = tid >> 5;

    const size_t base = ((size_t)(b * C + c) * H) * W + j0;
    const float* xg = xsrc + base;
    const float* eg = edge + b * HW + j0;

    #pragma unroll 4
    for (int i = wid; i < H; i += 8) {
        int sw = i * TW + (lane ^ (i & 31));
        xs[sw] = xg[(size_t)i * W + lane];
        ds[sw] = exp2f(-THC * fmaxf(eg[i * W + lane], 0.f));
    }
    __syncthreads();

    #pragma unroll
    for (int cc = 0; cc < 4; ++cc) {
        const int jl = wid * 4 + cc;
        float x[SEG], d[SEG];
        #pragma unroll
        for (int k = 0; k < SEG; ++k) {
            int i = lane * SEG + k;
            int sw = i * TW + (jl ^ (i & 31));
            x[k] = xs[sw]; d[k] = ds[sw];
        }

        float F = 0.f, A = 1.f;
        #pragma unroll
        for (int k = 0; k < SEG; ++k) { F = fmaf(F, d[k], x[k]); A *= d[k]; }
        float Af = A;
        wscan_fwd(Af, F, lane);
        float fin = __shfl_up_sync(0xffffffffu, F, 1);
        if (lane == 0) fin = 0.f;
        float f[SEG], v = fin;
        #pragma unroll
        for (int k = 0; k < SEG; ++k) { v = fmaf(v, d[k], x[k]); f[k] = v; }

        float G = 0.f, Ab = A;
        #pragma unroll
        for (int k = SEG - 1; k >= 0; --k) G = (G + x[k]) * d[k];
        wscan_bwd(Ab, G, lane);
        float gin = __shfl_down_sync(0xffffffffu, G, 1);
        if (lane == 31) gin = 0.f;

        float g = gin;
        #pragma unroll
        for (int k = SEG - 1; k >= 0; --k) {
            int i = lane * SEG + k;
            xs[i * TW + (jl ^ (i & 31))] = f[k] + g;
            g = (g + x[k]) * d[k];
        }
    }
    __syncthreads();

    float* ag = g_colA + base;
    #pragma unroll 4
    for (int i = wid; i < H; i += 8) {
        int sw = i * TW + (lane ^ (i & 31));
        ag[(size_t)i * W + lane] = xs[sw];
    }

    if (do_zc && c == 0) {                       // block-uniform predicate
        __syncthreads();                         // xs reads above done; reuse xs
        #pragma unroll
        for (int cc = 0; cc < 4; ++cc) {
            const int jl = wid * 4 + cc;
            float d[SEG];
            #pragma unroll
            for (int k = 0; k < SEG; ++k) {
                int i = lane * SEG + k;
                d[k] = ds[i * TW + (jl ^ (i & 31))];
            }
            float F = 0.f, A = 1.f;
            #pragma unroll
            for (int k = 0; k < SEG; ++k) { F = fmaf(F, d[k], 1.f); A *= d[k]; }
            float Af = A;
            wscan_fwd(Af, F, lane);
            float fin = __shfl_up_sync(0xffffffffu, F, 1);
            if (lane == 0) fin = 0.f;
            float f[SEG], v = fin;
            #pragma unroll
            for (int k = 0; k < SEG; ++k) { v = fmaf(v, d[k], 1.f); f[k] = v; }

            float G = 0.f, Ab = A;
            #pragma unroll
            for (int k = SEG - 1; k >= 0; --k) G = (G + 1.f) * d[k];
            wscan_bwd(Ab, G, lane);
            float gin = __shfl_down_sync(0xffffffffu, G, 1);
            if (lane == 31) gin = 0.f;

            float g = gin;
            #pragma unroll
            for (int k = SEG - 1; k >= 0; --k) {
                int i = lane * SEG + k;
                xs[i * TW + (jl ^ (i & 31))] = f[k] + g;   // zc incl diag
                g = (g + 1.f) * d[k];
            }
        }
        __syncthreads();
        float* zg = g_zc + b * HW + j0;
        #pragma unroll 4
        for (int i = wid; i < H; i += 8) {
            int sw = i * TW + (lane ^ (i & 31));
            zg[i * W + lane] = xs[sw];
        }
    }
}

// ---------------------------------------------------------------------------
// Row chain: combined x-scan + ones-scan (zr inline), combine + normalize.
// ---------------------------------------------------------------------------
__device__ void row_chain(int ch, int lane,
                          const float* __restrict__ xsrc,
                          const float* __restrict__ edge,
                          float* __restrict__ ob) {
    int b = ch / (C * H);
    int r = ch - b * (C * H);
    int c = r / H;
    int i = r - c * H;

    size_t off = ((size_t)(b * C + c) * H + i) * W + lane * SEG;
    size_t ro  = (size_t)b * HW + i * W + lane * SEG;

    const float2* xp = (const float2*)(xsrc + off);
    const float2* ep = (const float2*)(edge + ro);
    const float2* ap = (const float2*)(g_colA + off);
    const float2* zp = (const float2*)(g_zc + ro);

    float x[SEG], d[SEG], a[SEG], zc[SEG];
    #pragma unroll
    for (int k = 0; k < SEG / 2; ++k) { float2 t = xp[k]; x[2*k] = t.x; x[2*k+1] = t.y; }
    #pragma unroll
    for (int k = 0; k < SEG / 2; ++k) {
        float2 t = ep[k];
        d[2*k]   = exp2f(-THC * fmaxf(t.x, 0.f));
        d[2*k+1] = exp2f(-THC * fmaxf(t.y, 0.f));
    }
    #pragma unroll
    for (int k = 0; k < SEG / 2; ++k) { float2 t = ap[k]; a[2*k] = t.x; a[2*k+1] = t.y; }
    #pragma unroll
    for (int k = 0; k < SEG / 2; ++k) { float2 t = zp[k]; zc[2*k] = t.x; zc[2*k+1] = t.y; }

    float F = 0.f, F1 = 0.f, A = 1.f;
    #pragma unroll
    for (int k = 0; k < SEG; ++k) { F = fmaf(F, d[k], x[k]); F1 = fmaf(F1, d[k], 1.f); A *= d[k]; }
    float Af = A;
    wscan_fwd2(Af, F, F1, lane);
    float fin  = __shfl_up_sync(0xffffffffu, F, 1);
    float fin1 = __shfl_up_sync(0xffffffffu, F1, 1);
    if (lane == 0) { fin = 0.f; fin1 = 0.f; }
    float f[SEG], f1[SEG], v = fin, v1 = fin1;
    #pragma unroll
    for (int k = 0; k < SEG; ++k) {
        v  = fmaf(v,  d[k], x[k]); f[k]  = v;
        v1 = fmaf(v1, d[k], 1.f);  f1[k] = v1;
    }

    float G = 0.f, G1 = 0.f, Ab = A;
    #pragma unroll
    for (int k = SEG - 1; k >= 0; --k) { G = (G + x[k]) * d[k]; G1 = (G1 + 1.f) * d[k]; }
    wscan_bwd2(Ab, G, G1, lane);
    float gin  = __shfl_down_sync(0xffffffffu, G, 1);
    float gin1 = __shfl_down_sync(0xffffffffu, G1, 1);
    if (lane == 31) { gin = 0.f; gin1 = 0.f; }

    float o[SEG], g = gin, g1 = gin1;
    #pragma unroll
    for (int k = SEG - 1; k >= 0; --k) {
        float zr = f1[k] + g1 - 1.f;                     // row Z, diag removed
        o[k] = (a[k] + f[k] + g - x[k]) * (1.0f / (zc[k] + zr));
        g  = (g  + x[k]) * d[k];
        g1 = (g1 + 1.f) * d[k];
    }

    float2* op = (float2*)(ob + off);
    #pragma unroll
    for (int k = 0; k < SEG / 2; ++k)
        op[k] = make_float2(o[2*k], o[2*k+1]);
}

__device__ __forceinline__ void row_phase(int wg, int lane,
                                          const float* __restrict__ xsrc,
                                          const float* __restrict__ edge,
                                          float* __restrict__ ob) {
    #pragma unroll 1
    for (int q = 0; q < 4; ++q)                  // 3648 warps x 4 = 14592 chains
        row_chain(wg * 4 + q, lane, xsrc, edge, ob);
}

// ---------------------------------------------------------------------------
// Whole pipeline, one persistent launch, 5 grid barriers. iter fixed at 3.
// ---------------------------------------------------------------------------
__global__ __launch_bounds__(256, 4) void k_all(const float* __restrict__ mask,
                                                const float* __restrict__ edge,
                                                float* __restrict__ out) {
    __shared__ float sm[2 * H * TW];      // 48 KB
    float* xs = sm;
    float* ds = sm + H * TW;

    const int tid = threadIdx.x;
    const int lane = tid & 31;
    const int wg = blockIdx.x * 8 + (tid >> 5);

    // P1: column pass of iter 1 (+ zc from c==0 blocks)
    col_tile(mask, edge, xs, ds, 1);
    grid_bar();
    // P2: row pass iter 1: mask -> featA
    row_phase(wg, lane, mask, edge, g_featA);
    grid_bar();
    // P3/P4: iter 2
    col_tile(g_featA, edge, xs, ds, 0);
    grid_bar();
    row_phase(wg, lane, g_featA, edge, g_featB);
    grid_bar();
    // P5/P6: iter 3
    col_tile(g_featB, edge, xs, ds, 0);
    grid_bar();
    row_phase(wg, lane, g_featB, edge, out);
}

extern "C" void kernel_launch(void* const* d_in, const int* in_sizes, int n_in,
                              void* d_out, int out_size) {
    const float* mask = (const float*)d_in[0];
    const float* edge = (const float*)d_in[1];
    float* out = (float*)d_out;

    k_all<<<NBLK, 256>>>(mask, edge, out);
}